// round 8
// baseline (speedup 1.0000x reference)
#include <cuda_runtime.h>

#define B_  32
#define T_  4
#define L_  256
#define D_  768
#define H_  12
#define DH_ 64
#define N_  (B_*T_*L_)   // 32768 rows

// ---------------- scratch (no allocations allowed) ----------------
__device__ float g_Hq[(size_t)N_*D_];
__device__ float g_Hk[(size_t)N_*D_];
__device__ float g_Hv[(size_t)N_*D_];
__device__ float g_O [(size_t)N_*D_];
__device__ float g_Y [(size_t)N_*D_];

// ====== GEMM: C[m,n] = bias[n] + sum_k A[m,k]*W[n,k], single ascending-k FFMA chain ======
// (Eigen gebp on Grace: kc >= 768 -> no k-split; one serial fused chain per element.)
__global__ __launch_bounds__(256) void gemm_nt_kernel(
    const float* __restrict__ A, const float* __restrict__ W,
    const float* __restrict__ bias, float* __restrict__ C,
    int K, int Nn)
{
    __shared__ float As[8][128];
    __shared__ float Bs[8][128];
    const int tid  = threadIdx.x;
    const int tx   = tid & 15;
    const int ty   = tid >> 4;
    const int m0   = blockIdx.y * 128;
    const int n0   = blockIdx.x * 128;
    const int arow = tid >> 1;
    const int ak   = (tid & 1) * 4;

    const float* Aptr = A + (size_t)(m0 + arow) * K + ak;
    const float* Wptr = W + (size_t)(n0 + arow) * K + ak;

    float acc[8][8];
#pragma unroll
    for (int i = 0; i < 8; i++)
#pragma unroll
        for (int j = 0; j < 8; j++) acc[i][j] = 0.0f;

    for (int k0 = 0; k0 < K; k0 += 8) {
        float4 av = *(const float4*)(Aptr + k0);
        float4 wv = *(const float4*)(Wptr + k0);
        __syncthreads();
        As[ak + 0][arow] = av.x; As[ak + 1][arow] = av.y;
        As[ak + 2][arow] = av.z; As[ak + 3][arow] = av.w;
        Bs[ak + 0][arow] = wv.x; Bs[ak + 1][arow] = wv.y;
        Bs[ak + 2][arow] = wv.z; Bs[ak + 3][arow] = wv.w;
        __syncthreads();
#pragma unroll
        for (int kk = 0; kk < 8; kk++) {          // ascending k, single accumulator
            float a[8], b[8];
            *(float4*)&a[0] = *(const float4*)&As[kk][ty * 8 + 0];
            *(float4*)&a[4] = *(const float4*)&As[kk][ty * 8 + 4];
            *(float4*)&b[0] = *(const float4*)&Bs[kk][tx * 8 + 0];
            *(float4*)&b[4] = *(const float4*)&Bs[kk][tx * 8 + 4];
#pragma unroll
            for (int i = 0; i < 8; i++)
#pragma unroll
                for (int j = 0; j < 8; j++)
                    acc[i][j] = __fmaf_rn(a[i], b[j], acc[i][j]);
        }
    }

#pragma unroll
    for (int i = 0; i < 8; i++) {
        float* cp = C + (size_t)(m0 + ty * 8 + i) * Nn + n0 + tx * 8;
#pragma unroll
        for (int j = 0; j < 8; j++)
            cp[j] = __fadd_rn(acc[i][j], bias[n0 + tx * 8 + j]);
    }
}

// ===== LayerNorm + LIF, replicating XLA:CPU (LLVM/NEON VF=8) reduce exactly =====
// One warp per (b,l) row. Lane l in 0..7 serially sums x[8i+l] (96 ascending terms).
// Horizontal combine = halves-add then two pairwise steps: shfl-xor order 4, 1, 2
//   -> ((s0+s4)+(s1+s5)) + ((s2+s6)+(s3+s7)).
// Variance terms: separate mul then add (no FMA). IEEE div & sqrt everywhere.
__global__ __launch_bounds__(256) void ln_lif_kernel(
    const float* __restrict__ Hin, float* __restrict__ Sout,
    const float* __restrict__ gam, const float* __restrict__ bet, float thr)
{
    __shared__ float xs[8][768];
    const int w   = threadIdx.x >> 5;
    const int j   = threadIdx.x & 31;
    const int row = blockIdx.x * 8 + w;      // 0..B_*L_-1
    const int b   = row / L_;
    const int l   = row % L_;

    float g[24], be[24], v[24];
#pragma unroll
    for (int k = 0; k < 24; k++) {
        g[k]  = gam[j + 32 * k];
        be[k] = bet[j + 32 * k];
        v[k]  = 0.0f;
    }

    for (int t = 0; t < T_; t++) {
        const size_t off = ((size_t)(b * T_ + t) * L_ + l) * D_;
#pragma unroll
        for (int k = 0; k < 24; k++)
            xs[w][j + 32 * k] = Hin[off + j + 32 * k];
        __syncwarp();

        // ---- mean: 8-lane stride-8 serial partials ----
        float p = 0.0f;
        if (j < 8) {
#pragma unroll 8
            for (int i = 0; i < 96; i++)
                p = __fadd_rn(p, xs[w][8 * i + j]);
        }
        // halves-add (xor 4), then pairwise (xor 1), pairwise (xor 2)
        p = __fadd_rn(p, __shfl_xor_sync(0xffffffffu, p, 4));
        p = __fadd_rn(p, __shfl_xor_sync(0xffffffffu, p, 1));
        p = __fadd_rn(p, __shfl_xor_sync(0xffffffffu, p, 2));
        const float sum = __shfl_sync(0xffffffffu, p, 0);
        const float m = __fdiv_rn(sum, 768.0f);

        // ---- variance: (x-m)^2 as mul+add, same 8-lane structure ----
        float q = 0.0f;
        if (j < 8) {
#pragma unroll 8
            for (int i = 0; i < 96; i++) {
                const float d = __fsub_rn(xs[w][8 * i + j], m);
                q = __fadd_rn(q, __fmul_rn(d, d));
            }
        }
        q = __fadd_rn(q, __shfl_xor_sync(0xffffffffu, q, 4));
        q = __fadd_rn(q, __shfl_xor_sync(0xffffffffu, q, 1));
        q = __fadd_rn(q, __shfl_xor_sync(0xffffffffu, q, 2));
        const float sum2 = __shfl_sync(0xffffffffu, q, 0);
        const float var = __fdiv_rn(sum2, 768.0f);
        const float rs  = __fsqrt_rn(__fadd_rn(var, 1e-5f));

        // ---- normalize + LIF (separate correctly-rounded ops) ----
#pragma unroll
        for (int k = 0; k < 24; k++) {
            const float x = xs[w][j + 32 * k];
            const float d = __fsub_rn(x, m);
            const float h = __fadd_rn(__fmul_rn(__fdiv_rn(d, rs), g[k]), be[k]);
            // v = v + (h - v)/2  (divide by 2.0 exact)
            v[k] = __fadd_rn(v[k], __fdiv_rn(__fsub_rn(h, v[k]), 2.0f));
            const bool f = (__fsub_rn(v[k], thr) >= 0.0f);
            Sout[off + j + 32 * k] = f ? 1.0f : 0.0f;
            v[k] = f ? 0.0f : v[k];
        }
        __syncwarp();
    }
}

// ================= per-head non-softmax attention (exact integers) =================
__global__ __launch_bounds__(256) void attn_kernel(
    const float* __restrict__ Sq, const float* __restrict__ Sk,
    const float* __restrict__ Sv, float* __restrict__ O)
{
    __shared__ float Ks[64 * 64];
    __shared__ float Vs[64 * 64];
    const int h = blockIdx.x;
    const int t = blockIdx.y;
    const int b = blockIdx.z;
    const size_t rowbase = (size_t)(b * T_ + t) * L_;
    const int col = h * DH_;
    const int l = threadIdx.x;

    float q[64], o[64];
    {
        const float4* qp = (const float4*)(Sq + (rowbase + l) * D_ + col);
#pragma unroll
        for (int i = 0; i < 16; i++) {
            float4 v4 = qp[i];
            q[4 * i + 0] = v4.x; q[4 * i + 1] = v4.y;
            q[4 * i + 2] = v4.z; q[4 * i + 3] = v4.w;
        }
    }
#pragma unroll
    for (int d = 0; d < 64; d++) o[d] = 0.0f;

    for (int m0 = 0; m0 < L_; m0 += 64) {
        __syncthreads();
        for (int idx = threadIdx.x; idx < 64 * 64; idx += 256) {
            const int m = idx >> 6;
            const int d = idx & 63;
            const size_t goff = (rowbase + m0 + m) * D_ + col + d;
            Ks[idx] = Sk[goff];
            Vs[idx] = Sv[goff];
        }
        __syncthreads();
#pragma unroll 1
        for (int m = 0; m < 64; m++) {
            float a0 = 0.f, a1 = 0.f, a2 = 0.f, a3 = 0.f;
#pragma unroll
            for (int d = 0; d < 64; d += 4) {
                a0 += q[d + 0] * Ks[m * 64 + d + 0];
                a1 += q[d + 1] * Ks[m * 64 + d + 1];
                a2 += q[d + 2] * Ks[m * 64 + d + 2];
                a3 += q[d + 3] * Ks[m * 64 + d + 3];
            }
            const float a = (a0 + a1) + (a2 + a3);
#pragma unroll
            for (int d = 0; d < 64; d++)
                o[d] += a * Vs[m * 64 + d];
        }
    }

    float* op = O + (rowbase + l) * D_ + col;
#pragma unroll
    for (int d = 0; d < 64; d += 4) {
        float4 v4;
        v4.x = o[d + 0] * 0.25f; v4.y = o[d + 1] * 0.25f;
        v4.z = o[d + 2] * 0.25f; v4.w = o[d + 3] * 0.25f;
        *(float4*)(op + d) = v4;
    }
}

// ========== LIF over T on O (thr = 0.5, exact dyadic), in place ==========
__global__ __launch_bounds__(256) void lif2_kernel(float* __restrict__ IO)
{
    const int idx = blockIdx.x * 256 + threadIdx.x;   // over B*L*D
    const int b = idx / (L_ * D_);
    const int r = idx % (L_ * D_);
    float v = 0.0f;
#pragma unroll
    for (int t = 0; t < T_; t++) {
        const size_t off = ((size_t)(b * T_ + t)) * (size_t)(L_ * D_) + r;
        const float x = IO[off];
        v = __fadd_rn(v, __fdiv_rn(__fsub_rn(x, v), 2.0f));
        const bool f = (__fsub_rn(v, 0.5f) >= 0.0f);
        IO[off] = f ? 1.0f : 0.0f;
        v = f ? 0.0f : v;
    }
}

// ================= launch =================
extern "C" void kernel_launch(void* const* d_in, const int* in_sizes, int n_in,
                              void* d_out, int out_size)
{
    (void)in_sizes; (void)n_in; (void)out_size;
    const float* x   = (const float*)d_in[0];
    const float* qw  = (const float*)d_in[1];
    const float* qb  = (const float*)d_in[2];
    const float* qg  = (const float*)d_in[3];
    const float* qbe = (const float*)d_in[4];
    const float* kw  = (const float*)d_in[5];
    const float* kb  = (const float*)d_in[6];
    const float* kg  = (const float*)d_in[7];
    const float* kbe = (const float*)d_in[8];
    const float* vw  = (const float*)d_in[9];
    const float* vb  = (const float*)d_in[10];
    const float* vg  = (const float*)d_in[11];
    const float* vbe = (const float*)d_in[12];
    const float* lw  = (const float*)d_in[13];
    const float* lb  = (const float*)d_in[14];
    const float* lg  = (const float*)d_in[15];
    const float* lbe = (const float*)d_in[16];

    float *Hq, *Hk, *Hv, *O, *Y;
    cudaGetSymbolAddress((void**)&Hq, g_Hq);
    cudaGetSymbolAddress((void**)&Hk, g_Hk);
    cudaGetSymbolAddress((void**)&Hv, g_Hv);
    cudaGetSymbolAddress((void**)&O,  g_O);
    cudaGetSymbolAddress((void**)&Y,  g_Y);

    const dim3 gemm_grid(D_ / 128, N_ / 128);   // (6, 256)
    const int ln_blocks = (B_ * L_) / 8;        // warp per row

    // projections (single ascending-k fp32 FFMA chains)
    gemm_nt_kernel<<<gemm_grid, 256>>>(x, qw, qb, Hq, D_, D_);
    gemm_nt_kernel<<<gemm_grid, 256>>>(x, kw, kb, Hk, D_, D_);
    gemm_nt_kernel<<<gemm_grid, 256>>>(x, vw, vb, Hv, D_, D_);

    // LN + LIF (thr=1), NEON-VF8 reduce numerics, in place -> binary spikes
    ln_lif_kernel<<<ln_blocks, 256>>>(Hq, Hq, qg, qbe, 1.0f);
    ln_lif_kernel<<<ln_blocks, 256>>>(Hk, Hk, kg, kbe, 1.0f);
    ln_lif_kernel<<<ln_blocks, 256>>>(Hv, Hv, vg, vbe, 1.0f);

    // attention per (t,b,h) — exact integer arithmetic
    attn_kernel<<<dim3(H_, T_, B_), 256>>>(Hq, Hk, Hv, O);

    // LIF (thr=0.5) over T, exact dyadic, in place -> binary
    lif2_kernel<<<(B_ * L_ * D_) / 256, 256>>>(O);

    // final linear on binary spikes
    gemm_nt_kernel<<<gemm_grid, 256>>>(O, lw, lb, Y, D_, D_);

    // final LN + LIF (thr=1) -> output [B,T,L,D]
    ln_lif_kernel<<<ln_blocks, 256>>>(Y, (float*)d_out, lg, lbe, 1.0f);
}

// round 9
// speedup vs baseline: 1.1263x; 1.1263x over previous
#include <cuda_runtime.h>

#define B_  32
#define T_  4
#define L_  256
#define D_  768
#define H_  12
#define DH_ 64
#define N_  (B_*T_*L_)   // 32768 rows

// ---------------- scratch (no allocations allowed) ----------------
__device__ float g_Hq[(size_t)N_*D_];
__device__ float g_Hk[(size_t)N_*D_];
__device__ float g_Hv[(size_t)N_*D_];
__device__ float g_O [(size_t)N_*D_];
__device__ float g_Y [(size_t)N_*D_];

// ---------------- packed f32x2 helpers (sm_103a) ----------------
__device__ __forceinline__ unsigned long long pack2(float lo, float hi) {
    unsigned long long r;
    asm("mov.b64 %0, {%1, %2};" : "=l"(r) : "f"(lo), "f"(hi));
    return r;
}
__device__ __forceinline__ void unpack2(unsigned long long v, float& lo, float& hi) {
    asm("mov.b64 {%0, %1}, %2;" : "=f"(lo), "=f"(hi) : "l"(v));
}
// two independent IEEE fma.rn.f32 — bit-exact per lane
__device__ __forceinline__ unsigned long long ffma2(
    unsigned long long a, unsigned long long b, unsigned long long c) {
    unsigned long long d;
    asm("fma.rn.f32x2 %0, %1, %2, %3;" : "=l"(d) : "l"(a), "l"(b), "l"(c));
    return d;
}

// ====== GEMM: C[m,n] = bias[n] + sum_k A[m,k]*W[n,k], single ascending-k FMA chain ======
// FFMA2 pairs two OUTPUT COLUMNS per instruction; each element's serial chain is
// bitwise identical to the scalar version. 128x128 tile, BK=8, 256 thr, 8x8 micro-tile.
__global__ __launch_bounds__(256) void gemm_nt_kernel(
    const float* __restrict__ A, const float* __restrict__ W,
    const float* __restrict__ bias, float* __restrict__ C,
    int K, int Nn)
{
    __shared__ float As[8][128];
    __shared__ float Bs[8][128];
    const int tid  = threadIdx.x;
    const int tx   = tid & 15;
    const int ty   = tid >> 4;
    const int m0   = blockIdx.y * 128;
    const int n0   = blockIdx.x * 128;
    const int arow = tid >> 1;
    const int ak   = (tid & 1) * 4;

    const float* Aptr = A + (size_t)(m0 + arow) * K + ak;
    const float* Wptr = W + (size_t)(n0 + arow) * K + ak;

    unsigned long long acc2[8][4];   // [row][colpair]: cols 2j, 2j+1
#pragma unroll
    for (int i = 0; i < 8; i++)
#pragma unroll
        for (int j = 0; j < 4; j++) acc2[i][j] = 0ULL;

    for (int k0 = 0; k0 < K; k0 += 8) {
        float4 av = *(const float4*)(Aptr + k0);
        float4 wv = *(const float4*)(Wptr + k0);
        __syncthreads();
        As[ak + 0][arow] = av.x; As[ak + 1][arow] = av.y;
        As[ak + 2][arow] = av.z; As[ak + 3][arow] = av.w;
        Bs[ak + 0][arow] = wv.x; Bs[ak + 1][arow] = wv.y;
        Bs[ak + 2][arow] = wv.z; Bs[ak + 3][arow] = wv.w;
        __syncthreads();
#pragma unroll
        for (int kk = 0; kk < 8; kk++) {          // ascending k
            float a[8];
            *(float4*)&a[0] = *(const float4*)&As[kk][ty * 8 + 0];
            *(float4*)&a[4] = *(const float4*)&As[kk][ty * 8 + 4];
            const ulonglong2 b01 = *(const ulonglong2*)&Bs[kk][tx * 8 + 0];
            const ulonglong2 b23 = *(const ulonglong2*)&Bs[kk][tx * 8 + 4];
            unsigned long long b2[4];
            b2[0] = b01.x; b2[1] = b01.y; b2[2] = b23.x; b2[3] = b23.y;
#pragma unroll
            for (int i = 0; i < 8; i++) {
                const unsigned long long a2 = pack2(a[i], a[i]);
#pragma unroll
                for (int j = 0; j < 4; j++)
                    acc2[i][j] = ffma2(a2, b2[j], acc2[i][j]);
            }
        }
    }

#pragma unroll
    for (int i = 0; i < 8; i++) {
        float* cp = C + (size_t)(m0 + ty * 8 + i) * Nn + n0 + tx * 8;
#pragma unroll
        for (int j = 0; j < 4; j++) {
            float c0, c1;
            unpack2(acc2[i][j], c0, c1);
            cp[2 * j + 0] = __fadd_rn(c0, bias[n0 + tx * 8 + 2 * j + 0]);
            cp[2 * j + 1] = __fadd_rn(c1, bias[n0 + tx * 8 + 2 * j + 1]);
        }
    }
}

// ===== LayerNorm + LIF, XLA:CPU (LLVM/NEON VF=8) reduce — DO NOT TOUCH (bitwise) =====
__global__ __launch_bounds__(256) void ln_lif_kernel(
    const float* __restrict__ Hin, float* __restrict__ Sout,
    const float* __restrict__ gam, const float* __restrict__ bet, float thr)
{
    __shared__ float xs[8][768];
    const int w   = threadIdx.x >> 5;
    const int j   = threadIdx.x & 31;
    const int row = blockIdx.x * 8 + w;
    const int b   = row / L_;
    const int l   = row % L_;

    float g[24], be[24], v[24];
#pragma unroll
    for (int k = 0; k < 24; k++) {
        g[k]  = gam[j + 32 * k];
        be[k] = bet[j + 32 * k];
        v[k]  = 0.0f;
    }

    for (int t = 0; t < T_; t++) {
        const size_t off = ((size_t)(b * T_ + t) * L_ + l) * D_;
#pragma unroll
        for (int k = 0; k < 24; k++)
            xs[w][j + 32 * k] = Hin[off + j + 32 * k];
        __syncwarp();

        float p = 0.0f;
        if (j < 8) {
#pragma unroll 8
            for (int i = 0; i < 96; i++)
                p = __fadd_rn(p, xs[w][8 * i + j]);
        }
        p = __fadd_rn(p, __shfl_xor_sync(0xffffffffu, p, 4));
        p = __fadd_rn(p, __shfl_xor_sync(0xffffffffu, p, 1));
        p = __fadd_rn(p, __shfl_xor_sync(0xffffffffu, p, 2));
        const float sum = __shfl_sync(0xffffffffu, p, 0);
        const float m = __fdiv_rn(sum, 768.0f);

        float q = 0.0f;
        if (j < 8) {
#pragma unroll 8
            for (int i = 0; i < 96; i++) {
                const float d = __fsub_rn(xs[w][8 * i + j], m);
                q = __fadd_rn(q, __fmul_rn(d, d));
            }
        }
        q = __fadd_rn(q, __shfl_xor_sync(0xffffffffu, q, 4));
        q = __fadd_rn(q, __shfl_xor_sync(0xffffffffu, q, 1));
        q = __fadd_rn(q, __shfl_xor_sync(0xffffffffu, q, 2));
        const float sum2 = __shfl_sync(0xffffffffu, q, 0);
        const float var = __fdiv_rn(sum2, 768.0f);
        const float rs  = __fsqrt_rn(__fadd_rn(var, 1e-5f));

#pragma unroll
        for (int k = 0; k < 24; k++) {
            const float x = xs[w][j + 32 * k];
            const float d = __fsub_rn(x, m);
            const float h = __fadd_rn(__fmul_rn(__fdiv_rn(d, rs), g[k]), be[k]);
            v[k] = __fadd_rn(v[k], __fdiv_rn(__fsub_rn(h, v[k]), 2.0f));
            const bool f = (__fsub_rn(v[k], thr) >= 0.0f);
            Sout[off + j + 32 * k] = f ? 1.0f : 0.0f;
            v[k] = f ? 0.0f : v[k];
        }
        __syncwarp();
    }
}

// ===== per-head attention: QK via popcount (binary spikes), AV via FFMA2 =====
// All values exact integers in fp32 — any computation order is bit-equivalent.
__global__ __launch_bounds__(256) void attn_kernel(
    const float* __restrict__ Sq, const float* __restrict__ Sk,
    const float* __restrict__ Sv, float* __restrict__ O)
{
    __shared__ float Ks[64 * 64];
    __shared__ float Vs[64 * 64];
    __shared__ unsigned long long Km[64];
    const int h = blockIdx.x;
    const int t = blockIdx.y;
    const int b = blockIdx.z;
    const size_t rowbase = (size_t)(b * T_ + t) * L_;
    const int col = h * DH_;
    const int l = threadIdx.x;

    // build this query row's 64-bit spike mask
    unsigned long long qmask = 0ULL;
    {
        const float4* qp = (const float4*)(Sq + (rowbase + l) * D_ + col);
#pragma unroll
        for (int i = 0; i < 16; i++) {
            float4 v4 = qp[i];
            if (v4.x > 0.5f) qmask |= 1ULL << (4 * i + 0);
            if (v4.y > 0.5f) qmask |= 1ULL << (4 * i + 1);
            if (v4.z > 0.5f) qmask |= 1ULL << (4 * i + 2);
            if (v4.w > 0.5f) qmask |= 1ULL << (4 * i + 3);
        }
    }

    unsigned long long o2[32];
#pragma unroll
    for (int j = 0; j < 32; j++) o2[j] = 0ULL;

    for (int m0 = 0; m0 < L_; m0 += 64) {
        __syncthreads();
        for (int idx = threadIdx.x; idx < 64 * 64; idx += 256) {
            const int m = idx >> 6;
            const int d = idx & 63;
            const size_t goff = (rowbase + m0 + m) * D_ + col + d;
            Ks[idx] = Sk[goff];
            Vs[idx] = Sv[goff];
        }
        __syncthreads();
        // build K row masks (64 threads, one row each)
        if (threadIdx.x < 64) {
            const int m = threadIdx.x;
            unsigned long long km = 0ULL;
            const float4* kp = (const float4*)&Ks[m * 64];
#pragma unroll
            for (int i = 0; i < 16; i++) {
                float4 v4 = kp[i];
                if (v4.x > 0.5f) km |= 1ULL << (4 * i + 0);
                if (v4.y > 0.5f) km |= 1ULL << (4 * i + 1);
                if (v4.z > 0.5f) km |= 1ULL << (4 * i + 2);
                if (v4.w > 0.5f) km |= 1ULL << (4 * i + 3);
            }
            Km[m] = km;
        }
        __syncthreads();

#pragma unroll 1
        for (int m = 0; m < 64; m++) {
            const float a = (float)__popcll(qmask & Km[m]);   // exact small int
            const unsigned long long a2 = pack2(a, a);
            const ulonglong2* vp = (const ulonglong2*)&Vs[m * 64];
#pragma unroll
            for (int j = 0; j < 16; j++) {
                const ulonglong2 vv = vp[j];
                o2[2 * j + 0] = ffma2(a2, vv.x, o2[2 * j + 0]);
                o2[2 * j + 1] = ffma2(a2, vv.y, o2[2 * j + 1]);
            }
        }
    }

    float* op = O + (rowbase + l) * D_ + col;
#pragma unroll
    for (int j = 0; j < 32; j += 2) {
        float4 v4;
        float f0, f1, f2, f3;
        unpack2(o2[j],     f0, f1);
        unpack2(o2[j + 1], f2, f3);
        v4.x = f0 * 0.25f; v4.y = f1 * 0.25f;   // exact dyadic scaling
        v4.z = f2 * 0.25f; v4.w = f3 * 0.25f;
        *(float4*)(op + 2 * j) = v4;
    }
}

// ========== LIF over T on O (thr = 0.5, exact dyadic), in place ==========
__global__ __launch_bounds__(256) void lif2_kernel(float* __restrict__ IO)
{
    const int idx = blockIdx.x * 256 + threadIdx.x;   // over B*L*D
    const int b = idx / (L_ * D_);
    const int r = idx % (L_ * D_);
    float v = 0.0f;
#pragma unroll
    for (int t = 0; t < T_; t++) {
        const size_t off = ((size_t)(b * T_ + t)) * (size_t)(L_ * D_) + r;
        const float x = IO[off];
        v = __fadd_rn(v, __fdiv_rn(__fsub_rn(x, v), 2.0f));
        const bool f = (__fsub_rn(v, 0.5f) >= 0.0f);
        IO[off] = f ? 1.0f : 0.0f;
        v = f ? 0.0f : v;
    }
}

// ================= launch =================
extern "C" void kernel_launch(void* const* d_in, const int* in_sizes, int n_in,
                              void* d_out, int out_size)
{
    (void)in_sizes; (void)n_in; (void)out_size;
    const float* x   = (const float*)d_in[0];
    const float* qw  = (const float*)d_in[1];
    const float* qb  = (const float*)d_in[2];
    const float* qg  = (const float*)d_in[3];
    const float* qbe = (const float*)d_in[4];
    const float* kw  = (const float*)d_in[5];
    const float* kb  = (const float*)d_in[6];
    const float* kg  = (const float*)d_in[7];
    const float* kbe = (const float*)d_in[8];
    const float* vw  = (const float*)d_in[9];
    const float* vb  = (const float*)d_in[10];
    const float* vg  = (const float*)d_in[11];
    const float* vbe = (const float*)d_in[12];
    const float* lw  = (const float*)d_in[13];
    const float* lb  = (const float*)d_in[14];
    const float* lg  = (const float*)d_in[15];
    const float* lbe = (const float*)d_in[16];

    float *Hq, *Hk, *Hv, *O, *Y;
    cudaGetSymbolAddress((void**)&Hq, g_Hq);
    cudaGetSymbolAddress((void**)&Hk, g_Hk);
    cudaGetSymbolAddress((void**)&Hv, g_Hv);
    cudaGetSymbolAddress((void**)&O,  g_O);
    cudaGetSymbolAddress((void**)&Y,  g_Y);

    const dim3 gemm_grid(D_ / 128, N_ / 128);   // (6, 256)
    const int ln_blocks = (B_ * L_) / 8;        // warp per row

    // projections (single ascending-k fp32 chains via FFMA2 column pairs)
    gemm_nt_kernel<<<gemm_grid, 256>>>(x, qw, qb, Hq, D_, D_);
    gemm_nt_kernel<<<gemm_grid, 256>>>(x, kw, kb, Hk, D_, D_);
    gemm_nt_kernel<<<gemm_grid, 256>>>(x, vw, vb, Hv, D_, D_);

    // LN + LIF (thr=1), NEON-VF8 reduce numerics, in place -> binary spikes
    ln_lif_kernel<<<ln_blocks, 256>>>(Hq, Hq, qg, qbe, 1.0f);
    ln_lif_kernel<<<ln_blocks, 256>>>(Hk, Hk, kg, kbe, 1.0f);
    ln_lif_kernel<<<ln_blocks, 256>>>(Hv, Hv, vg, vbe, 1.0f);

    // attention per (t,b,h) — exact integer arithmetic (popc QK + FFMA2 AV)
    attn_kernel<<<dim3(H_, T_, B_), 256>>>(Hq, Hk, Hv, O);

    // LIF (thr=0.5) over T, exact dyadic, in place -> binary
    lif2_kernel<<<(B_ * L_ * D_) / 256, 256>>>(O);

    // final linear on binary spikes
    gemm_nt_kernel<<<gemm_grid, 256>>>(O, lw, lb, Y, D_, D_);

    // final LN + LIF (thr=1) -> output [B,T,L,D]
    ln_lif_kernel<<<ln_blocks, 256>>>(Y, (float*)d_out, lg, lbe, 1.0f);
}